// round 1
// baseline (speedup 1.0000x reference)
#include <cuda_runtime.h>
#include <math.h>

#define NB 8
#define NN 2048
#define ND 128

// ---- scratch (static device globals: allocation-free) ----
__device__ float g_h1[NB * NN * ND];     // 8 MB: post-linear activations
__device__ float g_rinv[NB * NN];        // per-row 1/max(||h1||, eps)
__device__ float g_agg[NB * NN * ND];    // 8 MB: aggregated output (inter-layer)

// ============================================================
// Kernel A: h1 = hin @ W + b ; rinv = 1/max(norm(h1), 1e-12)
// Grid: (B*N)/32 blocks, 256 threads. Each warp owns 4 rows x 128 cols.
// ============================================================
__global__ __launch_bounds__(256) void klinear(
    const float* __restrict__ xin, const float* __restrict__ W,
    const float* __restrict__ bias, int use_gagg)
{
    __shared__ float sH[32][128];
    const float* hin = use_gagg ? (const float*)g_agg : xin;
    int tid = threadIdx.x;
    size_t row0 = (size_t)blockIdx.x * 32;

    // load 32x128 input tile (float4, fully coalesced)
#pragma unroll
    for (int i = tid; i < 32 * 32; i += 256) {
        int r = i >> 5, kb = i & 31;
        *(float4*)&sH[r][4 * kb] = *(const float4*)(hin + (row0 + r) * (size_t)ND + 4 * kb);
    }
    __syncthreads();

    int wy = tid >> 5;   // warp id 0..7 -> rows 4*wy..4*wy+3
    int tx = tid & 31;   // lane -> cols 4*tx..4*tx+3

    float acc[4][4];
    {
        float4 bv = *(const float4*)(bias + 4 * tx);
#pragma unroll
        for (int i = 0; i < 4; i++) {
            acc[i][0] = bv.x; acc[i][1] = bv.y; acc[i][2] = bv.z; acc[i][3] = bv.w;
        }
    }

#pragma unroll 4
    for (int k = 0; k < ND; k++) {
        float4 wv = *(const float4*)(W + (size_t)k * ND + 4 * tx);
        float hr[4];
#pragma unroll
        for (int i = 0; i < 4; i++) hr[i] = sH[4 * wy + i][k];
#pragma unroll
        for (int i = 0; i < 4; i++) {
            acc[i][0] = fmaf(hr[i], wv.x, acc[i][0]);
            acc[i][1] = fmaf(hr[i], wv.y, acc[i][1]);
            acc[i][2] = fmaf(hr[i], wv.z, acc[i][2]);
            acc[i][3] = fmaf(hr[i], wv.w, acc[i][3]);
        }
    }

    // per-row norm (row fully owned by one warp) + store h1, rinv
#pragma unroll
    for (int i = 0; i < 4; i++) {
        float ss = acc[i][0] * acc[i][0] + acc[i][1] * acc[i][1]
                 + acc[i][2] * acc[i][2] + acc[i][3] * acc[i][3];
#pragma unroll
        for (int o = 16; o > 0; o >>= 1) ss += __shfl_xor_sync(0xffffffffu, ss, o);
        float ri = 1.0f / fmaxf(sqrtf(ss), 1e-12f);
        size_t row = row0 + 4 * wy + i;
        float4 v = {acc[i][0], acc[i][1], acc[i][2], acc[i][3]};
        *(float4*)(g_h1 + row * ND + 4 * tx) = v;
        if (tx == 0) g_rinv[row] = ri;
    }
}

// ============================================================
// Kernel B: fused  out[p,:] = sum_q ew[p,q]*(rinv_p*rinv_q*(h1_p . h1_q))*h1[q,:]
// Grid: (N/64, B), 256 threads, ~103KB dynamic smem (2 CTA/SM).
// Thread grid 16x16: phase1 each thread 4p x 4q of S, phase2 4p x 8c of out.
// ============================================================
#define BP 64
#define SH 132   // row stride (floats) for H tiles (64x128)
#define SS 68    // row stride for S / EW tiles (64x64)
#define KAGGR_SMEM ((64 * SH * 2 + 64 * SS * 2 + 128) * 4)

__global__ __launch_bounds__(256, 2) void kaggr(
    const float* __restrict__ ew, float* __restrict__ dout,
    int is_last, int do_relu)
{
    extern __shared__ float sm[];
    float* sHp = sm;                  // 64*132
    float* sHq = sHp + 64 * SH;       // 64*132
    float* sSt = sHq + 64 * SH;       // 64*68
    float* sEW = sSt + 64 * SS;       // 64*68
    float* srp = sEW + 64 * SS;       // 64
    float* srq = srp + 64;            // 64

    int tid = threadIdx.x;
    int b = blockIdx.y;
    int p0 = blockIdx.x * BP;
    const float* hb  = g_h1   + (size_t)b * NN * ND;
    const float* ewb = ew     + (size_t)b * NN * NN;
    const float* rb  = g_rinv + (size_t)b * NN;
    float* ob = (is_last ? dout : (float*)g_agg) + (size_t)b * NN * ND;

    // load persistent P tile
#pragma unroll
    for (int i = tid; i < 64 * 32; i += 256) {
        int r = i >> 5, kb = i & 31;
        *(float4*)(sHp + r * SH + 4 * kb) =
            *(const float4*)(hb + (size_t)(p0 + r) * ND + 4 * kb);
    }
    if (tid < 64) srp[tid] = rb[p0 + tid];

    int ty = tid >> 4;   // 0..15 -> p rows 4*ty..4*ty+3
    int tx = tid & 15;   // 0..15 -> q cols 4*tx.. (phase1), c cols 8*tx.. (phase2)

    float acc[4][8];
#pragma unroll
    for (int i = 0; i < 4; i++)
#pragma unroll
        for (int j = 0; j < 8; j++) acc[i][j] = 0.0f;

    for (int q0 = 0; q0 < NN; q0 += BP) {
        __syncthreads();   // prior phase2 done with sHq/sSt (also covers sHp load, iter 0)

        // load Q tile (h1 rows q0..q0+63) and EW tile (64x64)
#pragma unroll
        for (int i = tid; i < 64 * 32; i += 256) {
            int r = i >> 5, kb = i & 31;
            *(float4*)(sHq + r * SH + 4 * kb) =
                *(const float4*)(hb + (size_t)(q0 + r) * ND + 4 * kb);
        }
#pragma unroll
        for (int i = tid; i < 64 * 16; i += 256) {
            int r = i >> 4, kb = i & 15;
            *(float4*)(sEW + r * SS + 4 * kb) =
                *(const float4*)(ewb + (size_t)(p0 + r) * NN + q0 + 4 * kb);
        }
        if (tid < 64) srq[tid] = rb[q0 + tid];
        __syncthreads();

        // ---- phase 1: S[4x4] = Hp . Hq^T  (K=128, float4 over K) ----
        float s[4][4];
#pragma unroll
        for (int i = 0; i < 4; i++)
#pragma unroll
            for (int j = 0; j < 4; j++) s[i][j] = 0.0f;

#pragma unroll 2
        for (int k = 0; k < ND; k += 4) {
            float4 a[4], c[4];
#pragma unroll
            for (int i = 0; i < 4; i++)
                a[i] = *(const float4*)(sHp + (4 * ty + i) * SH + k);
#pragma unroll
            for (int j = 0; j < 4; j++)
                c[j] = *(const float4*)(sHq + (4 * tx + j) * SH + k);
#pragma unroll
            for (int i = 0; i < 4; i++)
#pragma unroll
                for (int j = 0; j < 4; j++) {
                    s[i][j] = fmaf(a[i].x, c[j].x, s[i][j]);
                    s[i][j] = fmaf(a[i].y, c[j].y, s[i][j]);
                    s[i][j] = fmaf(a[i].z, c[j].z, s[i][j]);
                    s[i][j] = fmaf(a[i].w, c[j].w, s[i][j]);
                }
        }
        {
            float rp[4], rq[4];
#pragma unroll
            for (int i = 0; i < 4; i++) rp[i] = srp[4 * ty + i];
#pragma unroll
            for (int j = 0; j < 4; j++) rq[j] = srq[4 * tx + j];
#pragma unroll
            for (int i = 0; i < 4; i++)
#pragma unroll
                for (int j = 0; j < 4; j++)
                    sSt[(4 * ty + i) * SS + 4 * tx + j] =
                        s[i][j] * rp[i] * rq[j] * sEW[(4 * ty + i) * SS + 4 * tx + j];
        }
        __syncthreads();

        // ---- phase 2: acc[4p][8c] += S[4p][q] * Hq[q][8c], q vectorized by 4 ----
#pragma unroll 2
        for (int qq = 0; qq < BP; qq += 4) {
            float4 sv[4];
#pragma unroll
            for (int i = 0; i < 4; i++)
                sv[i] = *(const float4*)(sSt + (4 * ty + i) * SS + qq);
#pragma unroll
            for (int u = 0; u < 2; u++) {
                int cb = tx * 8 + 4 * u;
                float4 h0 = *(const float4*)(sHq + (qq + 0) * SH + cb);
                float4 h1v = *(const float4*)(sHq + (qq + 1) * SH + cb);
                float4 h2 = *(const float4*)(sHq + (qq + 2) * SH + cb);
                float4 h3 = *(const float4*)(sHq + (qq + 3) * SH + cb);
#pragma unroll
                for (int i = 0; i < 4; i++) {
                    float* ap = &acc[i][4 * u];
                    ap[0] = fmaf(sv[i].x, h0.x, fmaf(sv[i].y, h1v.x,
                            fmaf(sv[i].z, h2.x, fmaf(sv[i].w, h3.x, ap[0]))));
                    ap[1] = fmaf(sv[i].x, h0.y, fmaf(sv[i].y, h1v.y,
                            fmaf(sv[i].z, h2.y, fmaf(sv[i].w, h3.y, ap[1]))));
                    ap[2] = fmaf(sv[i].x, h0.z, fmaf(sv[i].y, h1v.z,
                            fmaf(sv[i].z, h2.z, fmaf(sv[i].w, h3.z, ap[2]))));
                    ap[3] = fmaf(sv[i].x, h0.w, fmaf(sv[i].y, h1v.w,
                            fmaf(sv[i].z, h2.w, fmaf(sv[i].w, h3.w, ap[3]))));
                }
            }
        }
    }

    // ---- epilogue: optional relu, write out ----
#pragma unroll
    for (int i = 0; i < 4; i++) {
        size_t prow = (size_t)(p0 + 4 * ty + i) * ND;
#pragma unroll
        for (int u = 0; u < 2; u++) {
            float4 v = {acc[i][4 * u + 0], acc[i][4 * u + 1],
                        acc[i][4 * u + 2], acc[i][4 * u + 3]};
            if (do_relu) {
                v.x = fmaxf(v.x, 0.0f); v.y = fmaxf(v.y, 0.0f);
                v.z = fmaxf(v.z, 0.0f); v.w = fmaxf(v.w, 0.0f);
            }
            *(float4*)(ob + prow + tx * 8 + 4 * u) = v;
        }
    }
}

// ============================================================
extern "C" void kernel_launch(void* const* d_in, const int* in_sizes, int n_in,
                              void* d_out, int out_size)
{
    const float* x  = (const float*)d_in[0];
    const float* ew = (const float*)d_in[1];
    const float* W[3]    = {(const float*)d_in[2], (const float*)d_in[4], (const float*)d_in[6]};
    const float* bias[3] = {(const float*)d_in[3], (const float*)d_in[5], (const float*)d_in[7]};
    float* out = (float*)d_out;

    cudaFuncSetAttribute(kaggr, cudaFuncAttributeMaxDynamicSharedMemorySize, KAGGR_SMEM);

    dim3 gA(NB * NN / 32);
    dim3 gB(NN / BP, NB);

    for (int layer = 0; layer < 3; layer++) {
        klinear<<<gA, 256>>>(x, W[layer], bias[layer], layer > 0 ? 1 : 0);
        kaggr<<<gB, 256, KAGGR_SMEM>>>(ew, out, layer == 2 ? 1 : 0, layer < 2 ? 1 : 0);
    }
}

// round 6
// speedup vs baseline: 5.1334x; 5.1334x over previous
#include <cuda_runtime.h>
#include <cuda_bf16.h>
#include <math.h>

#define NB 8
#define NN 2048
#define ND 128
#define NT 16

// ---------------- scratch (allocation-free device globals) ----------------
__device__ __align__(16) unsigned short g_h1hi[NB * NN * ND];  // bf16 hi of h1 [b,n,d]
__device__ __align__(16) unsigned short g_h1lo[NB * NN * ND];  // bf16 lo (residual)
__device__ float g_rinv[NB * NN];
__device__ __align__(16) float g_agg[NB * NN * ND];            // inter-layer fp32

// ---------------- helpers ----------------
__device__ __forceinline__ unsigned smem_u32(const void* p) {
    unsigned a;
    asm("{ .reg .u64 t; cvta.to.shared.u64 t, %1; cvt.u32.u64 %0, t; }" : "=r"(a) : "l"(p));
    return a;
}
__device__ __forceinline__ void ldmx4(unsigned* r, unsigned a) {
    asm volatile("ldmatrix.sync.aligned.m8n8.x4.shared.b16 {%0,%1,%2,%3}, [%4];"
        : "=r"(r[0]), "=r"(r[1]), "=r"(r[2]), "=r"(r[3]) : "r"(a));
}
__device__ __forceinline__ void ldmx4t(unsigned* r, unsigned a) {
    asm volatile("ldmatrix.sync.aligned.m8n8.x4.trans.shared.b16 {%0,%1,%2,%3}, [%4];"
        : "=r"(r[0]), "=r"(r[1]), "=r"(r[2]), "=r"(r[3]) : "r"(a));
}
__device__ __forceinline__ void mma_bf16(float* d, const unsigned* a,
                                         unsigned b0, unsigned b1) {
    asm volatile("mma.sync.aligned.m16n8k16.row.col.f32.bf16.bf16.f32 "
        "{%0,%1,%2,%3},{%4,%5,%6,%7},{%8,%9},{%0,%1,%2,%3};"
        : "+f"(d[0]), "+f"(d[1]), "+f"(d[2]), "+f"(d[3])
        : "r"(a[0]), "r"(a[1]), "r"(a[2]), "r"(a[3]), "r"(b0), "r"(b1));
}
// pack two f32 -> bf16x2 (lo half = first arg)
__device__ __forceinline__ unsigned pack_bf16(float lo, float hi) {
    unsigned r;
    asm("cvt.rn.bf16x2.f32 %0, %1, %2;" : "=r"(r) : "f"(hi), "f"(lo));
    return r;
}

// ============================================================
// klinear: h1 = hin @ W + b ; rinv = 1/max(||h1||,eps);
// emits bf16 hi/lo split of h1 (row-major).
// ============================================================
__global__ __launch_bounds__(256) void klinear(
    const float* __restrict__ xin, const float* __restrict__ W,
    const float* __restrict__ bias, int use_gagg)
{
    __shared__ float sH[32][128];
    const float* hin = use_gagg ? (const float*)g_agg : xin;
    int tid = threadIdx.x;
    size_t row0 = (size_t)blockIdx.x * 32;

#pragma unroll
    for (int i = tid; i < 32 * 32; i += 256) {
        int r = i >> 5, kb = i & 31;
        *(float4*)&sH[r][4 * kb] = *(const float4*)(hin + (row0 + r) * (size_t)ND + 4 * kb);
    }
    __syncthreads();

    int wy = tid >> 5, tx = tid & 31;
    float acc[4][4];
    {
        float4 bv = *(const float4*)(bias + 4 * tx);
#pragma unroll
        for (int i = 0; i < 4; i++) {
            acc[i][0] = bv.x; acc[i][1] = bv.y; acc[i][2] = bv.z; acc[i][3] = bv.w;
        }
    }
#pragma unroll 4
    for (int k = 0; k < ND; k++) {
        float4 wv = *(const float4*)(W + (size_t)k * ND + 4 * tx);
        float hr[4];
#pragma unroll
        for (int i = 0; i < 4; i++) hr[i] = sH[4 * wy + i][k];
#pragma unroll
        for (int i = 0; i < 4; i++) {
            acc[i][0] = fmaf(hr[i], wv.x, acc[i][0]);
            acc[i][1] = fmaf(hr[i], wv.y, acc[i][1]);
            acc[i][2] = fmaf(hr[i], wv.z, acc[i][2]);
            acc[i][3] = fmaf(hr[i], wv.w, acc[i][3]);
        }
    }

#pragma unroll
    for (int i = 0; i < 4; i++) {
        float ss = acc[i][0] * acc[i][0] + acc[i][1] * acc[i][1]
                 + acc[i][2] * acc[i][2] + acc[i][3] * acc[i][3];
#pragma unroll
        for (int o = 16; o > 0; o >>= 1) ss += __shfl_xor_sync(0xffffffffu, ss, o);
        float ri = 1.0f / fmaxf(sqrtf(ss), 1e-12f);
        size_t row = row0 + 4 * wy + i;
        unsigned short ush[4], usl[4];
#pragma unroll
        for (int c2 = 0; c2 < 4; c2++) {
            __nv_bfloat16 hb = __float2bfloat16(acc[i][c2]);
            float res = acc[i][c2] - __bfloat162float(hb);
            ush[c2] = __bfloat16_as_ushort(hb);
            usl[c2] = __bfloat16_as_ushort(__float2bfloat16(res));
        }
        uint2 ph = make_uint2(ush[0] | ((unsigned)ush[1] << 16), ush[2] | ((unsigned)ush[3] << 16));
        uint2 pl = make_uint2(usl[0] | ((unsigned)usl[1] << 16), usl[2] | ((unsigned)usl[3] << 16));
        *(uint2*)(g_h1hi + row * ND + 4 * tx) = ph;
        *(uint2*)(g_h1lo + row * ND + 4 * tx) = pl;
        if (tx == 0) g_rinv[row] = ri;
    }
}

// ============================================================
// kaggr_mma: out[p,:] = sum_q ew[p,q]*rp*rq*(h1_p . h1_q) * h1[q,:]
// via mma.sync bf16 split (3 MMA per product). 8 warps x 16-row strips.
// ============================================================
#define SROWB 272                 // bytes per smem row (128+8 halfs)
#define OFF_HPH 0
#define OFF_HPL 34816
#define OFF_HQH 69632
#define OFF_HQL 104448
#define OFF_RQ  139264
#define SM_TOT  139776

__global__ __launch_bounds__(256) void kaggr_mma(
    const float* __restrict__ ew, float* __restrict__ dout,
    int is_last, int do_relu)
{
    extern __shared__ char sm[];
    unsigned sb = smem_u32(sm);
    int tid = threadIdx.x, wid = tid >> 5, lane = tid & 31;
    int b = blockIdx.y, p0 = blockIdx.x * 128;

    const unsigned short* hh = g_h1hi + (size_t)b * NN * ND;
    const unsigned short* hl = g_h1lo + (size_t)b * NN * ND;
    const float* ewb = ew + (size_t)b * NN * NN;
    const float* rb = g_rinv + (size_t)b * NN;
    float* ob = (is_last ? dout : (float*)g_agg) + (size_t)b * NN * ND;
    float* s_rq = (float*)(sm + OFF_RQ);

    // load persistent Hp hi/lo tile (padded rows): 128 rows x 16 uint4 chunks
#pragma unroll
    for (int f = tid; f < 2048; f += 256) {
        int r = f >> 4, ch = f & 15;
        *(uint4*)(sm + OFF_HPH + r * SROWB + ch * 16) =
            *(const uint4*)(hh + (size_t)(p0 + r) * ND + ch * 8);
        *(uint4*)(sm + OFF_HPL + r * SROWB + ch * 16) =
            *(const uint4*)(hl + (size_t)(p0 + r) * ND + ch * 8);
    }

    int g = lane >> 2, c = lane & 3;
    int mrow = wid * 16;
    float rp0 = rb[p0 + mrow + g];
    float rp1 = rb[p0 + mrow + g + 8];
    const float* ew0 = ewb + (size_t)(p0 + mrow + g) * NN;
    const float* ew1 = ewb + (size_t)(p0 + mrow + g + 8) * NN;

    // per-lane ldmatrix base offsets
    int grp = lane >> 3, wi = lane & 7;
    unsigned offA = (unsigned)((mrow + wi + (grp & 1) * 8) * SROWB + (grp >> 1) * 16);
    unsigned offB = (unsigned)((wi + (grp >> 1) * 8) * SROWB + (grp & 1) * 16);
    unsigned offT = (unsigned)((wi + (grp & 1) * 8) * SROWB + (grp >> 1) * 16);

    float o[16][4];
#pragma unroll
    for (int j = 0; j < 16; j++)
#pragma unroll
        for (int k = 0; k < 4; k++) o[j][k] = 0.0f;

    for (int t = 0; t < NT; t++) {
        int q0 = t << 7;
        __syncthreads();   // all warps done reading Hq from previous iter
#pragma unroll
        for (int f = tid; f < 2048; f += 256) {
            int r = f >> 4, ch = f & 15;
            *(uint4*)(sm + OFF_HQH + r * SROWB + ch * 16) =
                *(const uint4*)(hh + (size_t)(q0 + r) * ND + ch * 8);
            *(uint4*)(sm + OFF_HQL + r * SROWB + ch * 16) =
                *(const uint4*)(hl + (size_t)(q0 + r) * ND + ch * 8);
        }
        if (tid < 128) s_rq[tid] = rb[q0 + tid];
        __syncthreads();

        unsigned SAh[8][4], SAl[8][4];

        // ---- GEMM1 in two n-halves (keeps S register footprint at 32) ----
#pragma unroll
        for (int nh = 0; nh < 2; nh++) {
            float s[8][4];
#pragma unroll
            for (int j = 0; j < 8; j++)
#pragma unroll
                for (int k = 0; k < 4; k++) s[j][k] = 0.0f;

#pragma unroll
            for (int kk = 0; kk < 8; kk++) {
                unsigned ah[4], al[4];
                ldmx4(ah, sb + OFF_HPH + offA + kk * 32);
                ldmx4(al, sb + OFF_HPL + offA + kk * 32);
#pragma unroll
                for (int np = 0; np < 4; np++) {
                    unsigned bh[4], bl[4];
                    unsigned nb = (unsigned)((nh * 4 + np) * 16 * SROWB);
                    ldmx4(bh, sb + OFF_HQH + offB + nb + kk * 32);
                    ldmx4(bl, sb + OFF_HQL + offB + nb + kk * 32);
                    mma_bf16(s[2 * np], ah, bh[0], bh[1]);
                    mma_bf16(s[2 * np], al, bh[0], bh[1]);
                    mma_bf16(s[2 * np], ah, bl[0], bl[1]);
                    mma_bf16(s[2 * np + 1], ah, bh[2], bh[3]);
                    mma_bf16(s[2 * np + 1], al, bh[2], bh[3]);
                    mma_bf16(s[2 * np + 1], ah, bl[2], bl[3]);
                }
            }

            // ---- scale by rp*rq*ew + bf16 split -> A fragments for GEMM2 ----
#pragma unroll
            for (int tl = 0; tl < 8; tl++) {
                int j = nh * 8 + tl;
                int col = 8 * j + 2 * c;
                float2 rq2 = *(float2*)&s_rq[col];
                float2 e0 = *(const float2*)(ew0 + q0 + col);
                float2 e1 = *(const float2*)(ew1 + q0 + col);
                float v0 = s[tl][0] * (rp0 * rq2.x * e0.x);
                float v1 = s[tl][1] * (rp0 * rq2.y * e0.y);
                float v2 = s[tl][2] * (rp1 * rq2.x * e1.x);
                float v3 = s[tl][3] * (rp1 * rq2.y * e1.y);
                __nv_bfloat16 h0 = __float2bfloat16(v0);
                __nv_bfloat16 h1v = __float2bfloat16(v1);
                __nv_bfloat16 h2 = __float2bfloat16(v2);
                __nv_bfloat16 h3 = __float2bfloat16(v3);
                float r0v = v0 - __bfloat162float(h0);
                float r1v = v1 - __bfloat162float(h1v);
                float r2v = v2 - __bfloat162float(h2);
                float r3v = v3 - __bfloat162float(h3);
                int kk2 = j >> 1, sl = (j & 1) * 2;
                SAh[kk2][sl]     = (unsigned)__bfloat16_as_ushort(h0)
                                 | ((unsigned)__bfloat16_as_ushort(h1v) << 16);
                SAh[kk2][sl + 1] = (unsigned)__bfloat16_as_ushort(h2)
                                 | ((unsigned)__bfloat16_as_ushort(h3) << 16);
                SAl[kk2][sl]     = pack_bf16(r0v, r1v);
                SAl[kk2][sl + 1] = pack_bf16(r2v, r3v);
            }
        }

        // ---- GEMM2: o += S_split x Hq (B via ldmatrix.trans) ----
#pragma unroll
        for (int kk = 0; kk < 8; kk++) {
#pragma unroll
            for (int np = 0; np < 8; np++) {
                unsigned bh[4], bl[4];
                unsigned kb = (unsigned)(kk * 16 * SROWB);
                ldmx4t(bh, sb + OFF_HQH + offT + kb + np * 32);
                ldmx4t(bl, sb + OFF_HQL + offT + kb + np * 32);
                mma_bf16(o[2 * np], SAh[kk], bh[0], bh[1]);
                mma_bf16(o[2 * np], SAl[kk], bh[0], bh[1]);
                mma_bf16(o[2 * np], SAh[kk], bl[0], bl[1]);
                mma_bf16(o[2 * np + 1], SAh[kk], bh[2], bh[3]);
                mma_bf16(o[2 * np + 1], SAl[kk], bh[2], bh[3]);
                mma_bf16(o[2 * np + 1], SAh[kk], bl[2], bl[3]);
            }
        }
    }

    // ---- epilogue: optional relu, fragment-layout stores (float2) ----
    float* r0p = ob + (size_t)(p0 + mrow + g) * ND;
    float* r1p = ob + (size_t)(p0 + mrow + g + 8) * ND;
#pragma unroll
    for (int j = 0; j < 16; j++) {
        float2 v0 = make_float2(o[j][0], o[j][1]);
        float2 v1 = make_float2(o[j][2], o[j][3]);
        if (do_relu) {
            v0.x = fmaxf(v0.x, 0.0f); v0.y = fmaxf(v0.y, 0.0f);
            v1.x = fmaxf(v1.x, 0.0f); v1.y = fmaxf(v1.y, 0.0f);
        }
        *(float2*)(r0p + 8 * j + 2 * c) = v0;
        *(float2*)(r1p + 8 * j + 2 * c) = v1;
    }
}

// ============================================================
extern "C" void kernel_launch(void* const* d_in, const int* in_sizes, int n_in,
                              void* d_out, int out_size)
{
    const float* x  = (const float*)d_in[0];
    const float* ew = (const float*)d_in[1];
    const float* W[3]    = {(const float*)d_in[2], (const float*)d_in[4], (const float*)d_in[6]};
    const float* bias[3] = {(const float*)d_in[3], (const float*)d_in[5], (const float*)d_in[7]};
    float* out = (float*)d_out;

    cudaFuncSetAttribute(kaggr_mma, cudaFuncAttributeMaxDynamicSharedMemorySize, SM_TOT);

    dim3 gA(NB * NN / 32);
    dim3 gB(NN / 128, NB);

    for (int layer = 0; layer < 3; layer++) {
        klinear<<<gA, 256>>>(x, W[layer], bias[layer], layer > 0 ? 1 : 0);
        kaggr_mma<<<gB, 256, SM_TOT>>>(ew, out, layer == 2 ? 1 : 0, layer < 2 ? 1 : 0);
    }
}

// round 7
// speedup vs baseline: 5.3580x; 1.0437x over previous
#include <cuda_runtime.h>
#include <cuda_bf16.h>
#include <math.h>

#define NB 8
#define NN 2048
#define ND 128
#define NT 16

// ---------------- scratch (allocation-free device globals) ----------------
__device__ __align__(16) unsigned short g_h1hi[NB * NN * ND];  // bf16 hi of h1 [b,n,d]
__device__ __align__(16) unsigned short g_h1lo[NB * NN * ND];  // bf16 lo (residual)
__device__ __align__(16) float g_rinv[NB * NN];
__device__ __align__(16) float g_agg[NB * NN * ND];            // inter-layer fp32

// ---------------- helpers ----------------
__device__ __forceinline__ unsigned smem_u32(const void* p) {
    unsigned a;
    asm("{ .reg .u64 t; cvta.to.shared.u64 t, %1; cvt.u32.u64 %0, t; }" : "=r"(a) : "l"(p));
    return a;
}
__device__ __forceinline__ void ldmx4(unsigned* r, unsigned a) {
    asm volatile("ldmatrix.sync.aligned.m8n8.x4.shared.b16 {%0,%1,%2,%3}, [%4];"
        : "=r"(r[0]), "=r"(r[1]), "=r"(r[2]), "=r"(r[3]) : "r"(a));
}
__device__ __forceinline__ void ldmx4t(unsigned* r, unsigned a) {
    asm volatile("ldmatrix.sync.aligned.m8n8.x4.trans.shared.b16 {%0,%1,%2,%3}, [%4];"
        : "=r"(r[0]), "=r"(r[1]), "=r"(r[2]), "=r"(r[3]) : "r"(a));
}
__device__ __forceinline__ void mma_bf16(float* d, const unsigned* a,
                                         unsigned b0, unsigned b1) {
    asm volatile("mma.sync.aligned.m16n8k16.row.col.f32.bf16.bf16.f32 "
        "{%0,%1,%2,%3},{%4,%5,%6,%7},{%8,%9},{%0,%1,%2,%3};"
        : "+f"(d[0]), "+f"(d[1]), "+f"(d[2]), "+f"(d[3])
        : "r"(a[0]), "r"(a[1]), "r"(a[2]), "r"(a[3]), "r"(b0), "r"(b1));
}
__device__ __forceinline__ unsigned pack_bf16(float lo, float hi) {
    unsigned r;
    asm("cvt.rn.bf16x2.f32 %0, %1, %2;" : "=r"(r) : "f"(hi), "f"(lo));
    return r;
}
#define CP_ASYNC16(dst, src) \
    asm volatile("cp.async.cg.shared.global [%0], [%1], 16;" \
        :: "r"((unsigned)(dst)), "l"(src) : "memory")
#define CP_COMMIT() asm volatile("cp.async.commit_group;" ::: "memory")
#define CP_WAIT0()  asm volatile("cp.async.wait_group 0;" ::: "memory")

// ============================================================
// klinear: h1 = hin @ W + b ; rinv = 1/max(||h1||,eps);
// emits bf16 hi/lo split of h1 (row-major).
// ============================================================
__global__ __launch_bounds__(256) void klinear(
    const float* __restrict__ xin, const float* __restrict__ W,
    const float* __restrict__ bias, int use_gagg)
{
    __shared__ float sH[32][128];
    const float* hin = use_gagg ? (const float*)g_agg : xin;
    int tid = threadIdx.x;
    size_t row0 = (size_t)blockIdx.x * 32;

#pragma unroll
    for (int i = tid; i < 32 * 32; i += 256) {
        int r = i >> 5, kb = i & 31;
        *(float4*)&sH[r][4 * kb] = *(const float4*)(hin + (row0 + r) * (size_t)ND + 4 * kb);
    }
    __syncthreads();

    int wy = tid >> 5, tx = tid & 31;
    float acc[4][4];
    {
        float4 bv = *(const float4*)(bias + 4 * tx);
#pragma unroll
        for (int i = 0; i < 4; i++) {
            acc[i][0] = bv.x; acc[i][1] = bv.y; acc[i][2] = bv.z; acc[i][3] = bv.w;
        }
    }
#pragma unroll 4
    for (int k = 0; k < ND; k++) {
        float4 wv = *(const float4*)(W + (size_t)k * ND + 4 * tx);
        float hr[4];
#pragma unroll
        for (int i = 0; i < 4; i++) hr[i] = sH[4 * wy + i][k];
#pragma unroll
        for (int i = 0; i < 4; i++) {
            acc[i][0] = fmaf(hr[i], wv.x, acc[i][0]);
            acc[i][1] = fmaf(hr[i], wv.y, acc[i][1]);
            acc[i][2] = fmaf(hr[i], wv.z, acc[i][2]);
            acc[i][3] = fmaf(hr[i], wv.w, acc[i][3]);
        }
    }

#pragma unroll
    for (int i = 0; i < 4; i++) {
        float ss = acc[i][0] * acc[i][0] + acc[i][1] * acc[i][1]
                 + acc[i][2] * acc[i][2] + acc[i][3] * acc[i][3];
#pragma unroll
        for (int o = 16; o > 0; o >>= 1) ss += __shfl_xor_sync(0xffffffffu, ss, o);
        float ri = 1.0f / fmaxf(sqrtf(ss), 1e-12f);
        size_t row = row0 + 4 * wy + i;
        unsigned short ush[4], usl[4];
#pragma unroll
        for (int c2 = 0; c2 < 4; c2++) {
            __nv_bfloat16 hb = __float2bfloat16(acc[i][c2]);
            float res = acc[i][c2] - __bfloat162float(hb);
            ush[c2] = __bfloat16_as_ushort(hb);
            usl[c2] = __bfloat16_as_ushort(__float2bfloat16(res));
        }
        uint2 ph = make_uint2(ush[0] | ((unsigned)ush[1] << 16), ush[2] | ((unsigned)ush[3] << 16));
        uint2 pl = make_uint2(usl[0] | ((unsigned)usl[1] << 16), usl[2] | ((unsigned)usl[3] << 16));
        *(uint2*)(g_h1hi + row * ND + 4 * tx) = ph;
        *(uint2*)(g_h1lo + row * ND + 4 * tx) = pl;
        if (tx == 0) g_rinv[row] = ri;
    }
}

// ============================================================
// kaggr_mma: out[p,:] = sum_q ew[p,q]*rp*rq*(h1_p . h1_q) * h1[q,:]
// mma.sync bf16 split; cp.async double-buffered Hq; GEMM2 interleaved per n-half.
// ============================================================
#define SROWB 272                 // bytes per smem row (128+8 halfs)
#define TILEB 34816               // one 128-row tile (hi or lo)
#define OFF_HPH 0
#define OFF_HPL TILEB
#define OFF_HQ0 (2 * TILEB)       // buffer 0: hi at +0, lo at +TILEB
#define OFF_HQ1 (4 * TILEB)       // buffer 1
#define OFF_RQ  (6 * TILEB)       // 2 x 512B
#define SM_TOT  (6 * TILEB + 1024)

__global__ __launch_bounds__(256) void kaggr_mma(
    const float* __restrict__ ew, float* __restrict__ dout,
    int is_last, int do_relu)
{
    extern __shared__ char sm[];
    unsigned sb = smem_u32(sm);
    int tid = threadIdx.x, wid = tid >> 5, lane = tid & 31;
    int b = blockIdx.y, p0 = blockIdx.x * 128;

    const unsigned short* hh = g_h1hi + (size_t)b * NN * ND;
    const unsigned short* hl = g_h1lo + (size_t)b * NN * ND;
    const float* ewb = ew + (size_t)b * NN * NN;
    const float* rb = g_rinv + (size_t)b * NN;
    float* ob = (is_last ? dout : (float*)g_agg) + (size_t)b * NN * ND;

    // persistent Hp hi/lo tile (plain loads; once per CTA)
#pragma unroll
    for (int f = tid; f < 2048; f += 256) {
        int r = f >> 4, ch = f & 15;
        *(uint4*)(sm + OFF_HPH + r * SROWB + ch * 16) =
            *(const uint4*)(hh + (size_t)(p0 + r) * ND + ch * 8);
        *(uint4*)(sm + OFF_HPL + r * SROWB + ch * 16) =
            *(const uint4*)(hl + (size_t)(p0 + r) * ND + ch * 8);
    }

    int g = lane >> 2, c = lane & 3;
    int mrow = wid * 16;
    float rp0 = rb[p0 + mrow + g];
    float rp1 = rb[p0 + mrow + g + 8];
    const float* ew0 = ewb + (size_t)(p0 + mrow + g) * NN;
    const float* ew1 = ewb + (size_t)(p0 + mrow + g + 8) * NN;

    // per-lane ldmatrix base offsets
    int grp = lane >> 3, wi = lane & 7;
    unsigned offA = (unsigned)((mrow + wi + (grp & 1) * 8) * SROWB + (grp >> 1) * 16);
    unsigned offB = (unsigned)((wi + (grp >> 1) * 8) * SROWB + (grp & 1) * 16);
    unsigned offT = (unsigned)((wi + (grp & 1) * 8) * SROWB + (grp >> 1) * 16);

    float o[16][4];
#pragma unroll
    for (int j = 0; j < 16; j++)
#pragma unroll
        for (int k = 0; k < 4; k++) o[j][k] = 0.0f;

    // ---- cp.async tile fetch for q-tile t into buffer ----
    auto issue_tile = [&](int t, unsigned bufoff) {
        int q0 = t << 7;
#pragma unroll
        for (int f = tid; f < 2048; f += 256) {
            int r = f >> 4, ch = f & 15;
            CP_ASYNC16(sb + bufoff + r * SROWB + ch * 16,
                       hh + (size_t)(q0 + r) * ND + ch * 8);
            CP_ASYNC16(sb + bufoff + TILEB + r * SROWB + ch * 16,
                       hl + (size_t)(q0 + r) * ND + ch * 8);
        }
        if (tid < 32) CP_ASYNC16(sb + OFF_RQ + ((unsigned)(t & 1) << 9) + tid * 16,
                                 rb + q0 + tid * 4);
        CP_COMMIT();
    };

    issue_tile(0, OFF_HQ0);

    for (int t = 0; t < NT; t++) {
        unsigned bufoff = (t & 1) ? OFF_HQ1 : OFF_HQ0;
        CP_WAIT0();
        __syncthreads();   // tile t landed; everyone done reading other buffer
        if (t + 1 < NT) issue_tile(t + 1, (t & 1) ? OFF_HQ0 : OFF_HQ1);

        int q0 = t << 7;
        const float* s_rq = (const float*)(sm + OFF_RQ + ((unsigned)(t & 1) << 9));

#pragma unroll
        for (int nh = 0; nh < 2; nh++) {
            // EW prefetch for this n-half (hidden under GEMM1 MMAs)
            float2 eq0[8], eq1[8];
#pragma unroll
            for (int tl = 0; tl < 8; tl++) {
                int col = q0 + (nh * 8 + tl) * 8 + 2 * c;
                eq0[tl] = *(const float2*)(ew0 + col);
                eq1[tl] = *(const float2*)(ew1 + col);
            }

            // ---- GEMM1: S-half = Hp . Hq^T ----
            float s[8][4];
#pragma unroll
            for (int j = 0; j < 8; j++)
#pragma unroll
                for (int k = 0; k < 4; k++) s[j][k] = 0.0f;

#pragma unroll
            for (int kk = 0; kk < 8; kk++) {
                unsigned ah[4], al[4];
                ldmx4(ah, sb + OFF_HPH + offA + kk * 32);
                ldmx4(al, sb + OFF_HPL + offA + kk * 32);
#pragma unroll
                for (int np = 0; np < 4; np++) {
                    unsigned bh[4], bl[4];
                    unsigned nb = bufoff + (unsigned)((nh * 4 + np) * 16 * SROWB);
                    ldmx4(bh, sb + nb + offB + kk * 32);
                    ldmx4(bl, sb + nb + TILEB + offB + kk * 32);
                    mma_bf16(s[2 * np], ah, bh[0], bh[1]);
                    mma_bf16(s[2 * np], al, bh[0], bh[1]);
                    mma_bf16(s[2 * np], ah, bl[0], bl[1]);
                    mma_bf16(s[2 * np + 1], ah, bh[2], bh[3]);
                    mma_bf16(s[2 * np + 1], al, bh[2], bh[3]);
                    mma_bf16(s[2 * np + 1], ah, bl[2], bl[3]);
                }
            }

            // ---- scale + bf16 split -> A fragments (4 kk groups) ----
            unsigned SAh[4][4], SAl[4][4];
#pragma unroll
            for (int tl = 0; tl < 8; tl++) {
                int col = (nh * 8 + tl) * 8 + 2 * c;
                float2 rq2 = *(const float2*)&s_rq[col];
                float2 e0 = eq0[tl];
                float2 e1 = eq1[tl];
                float v0 = s[tl][0] * (rp0 * rq2.x * e0.x);
                float v1 = s[tl][1] * (rp0 * rq2.y * e0.y);
                float v2 = s[tl][2] * (rp1 * rq2.x * e1.x);
                float v3 = s[tl][3] * (rp1 * rq2.y * e1.y);
                __nv_bfloat16 h0 = __float2bfloat16(v0);
                __nv_bfloat16 h1v = __float2bfloat16(v1);
                __nv_bfloat16 h2 = __float2bfloat16(v2);
                __nv_bfloat16 h3 = __float2bfloat16(v3);
                float r0v = v0 - __bfloat162float(h0);
                float r1v = v1 - __bfloat162float(h1v);
                float r2v = v2 - __bfloat162float(h2);
                float r3v = v3 - __bfloat162float(h3);
                int kl = tl >> 1, sl = (tl & 1) * 2;
                SAh[kl][sl]     = (unsigned)__bfloat16_as_ushort(h0)
                                | ((unsigned)__bfloat16_as_ushort(h1v) << 16);
                SAh[kl][sl + 1] = (unsigned)__bfloat16_as_ushort(h2)
                                | ((unsigned)__bfloat16_as_ushort(h3) << 16);
                SAl[kl][sl]     = pack_bf16(r0v, r1v);
                SAl[kl][sl + 1] = pack_bf16(r2v, r3v);
            }

            // ---- GEMM2 (interleaved): o += S_half x Hq over kk in this half ----
#pragma unroll
            for (int kl = 0; kl < 4; kl++) {
                unsigned kb = bufoff + (unsigned)((nh * 4 + kl) * 16 * SROWB);
#pragma unroll
                for (int np = 0; np < 8; np++) {
                    unsigned bh[4], bl[4];
                    ldmx4t(bh, sb + kb + offT + np * 32);
                    ldmx4t(bl, sb + kb + TILEB + offT + np * 32);
                    mma_bf16(o[2 * np], SAh[kl], bh[0], bh[1]);
                    mma_bf16(o[2 * np], SAl[kl], bh[0], bh[1]);
                    mma_bf16(o[2 * np], SAh[kl], bl[0], bl[1]);
                    mma_bf16(o[2 * np + 1], SAh[kl], bh[2], bh[3]);
                    mma_bf16(o[2 * np + 1], SAl[kl], bh[2], bh[3]);
                    mma_bf16(o[2 * np + 1], SAh[kl], bl[2], bl[3]);
                }
            }
        }
    }

    // ---- epilogue: optional relu, fragment-layout stores (float2) ----
    float* r0p = ob + (size_t)(p0 + mrow + g) * ND;
    float* r1p = ob + (size_t)(p0 + mrow + g + 8) * ND;
#pragma unroll
    for (int j = 0; j < 16; j++) {
        float2 v0 = make_float2(o[j][0], o[j][1]);
        float2 v1 = make_float2(o[j][2], o[j][3]);
        if (do_relu) {
            v0.x = fmaxf(v0.x, 0.0f); v0.y = fmaxf(v0.y, 0.0f);
            v1.x = fmaxf(v1.x, 0.0f); v1.y = fmaxf(v1.y, 0.0f);
        }
        *(float2*)(r0p + 8 * j + 2 * c) = v0;
        *(float2*)(r1p + 8 * j + 2 * c) = v1;
    }
}

// ============================================================
extern "C" void kernel_launch(void* const* d_in, const int* in_sizes, int n_in,
                              void* d_out, int out_size)
{
    const float* x  = (const float*)d_in[0];
    const float* ew = (const float*)d_in[1];
    const float* W[3]    = {(const float*)d_in[2], (const float*)d_in[4], (const float*)d_in[6]};
    const float* bias[3] = {(const float*)d_in[3], (const float*)d_in[5], (const float*)d_in[7]};
    float* out = (float*)d_out;

    cudaFuncSetAttribute(kaggr_mma, cudaFuncAttributeMaxDynamicSharedMemorySize, SM_TOT);

    dim3 gA(NB * NN / 32);
    dim3 gB(NN / 128, NB);

    for (int layer = 0; layer < 3; layer++) {
        klinear<<<gA, 256>>>(x, W[layer], bias[layer], layer > 0 ? 1 : 0);
        kaggr_mma<<<gB, 256, SM_TOT>>>(ew, out, layer == 2 ? 1 : 0, layer < 2 ? 1 : 0);
    }
}